// round 5
// baseline (speedup 1.0000x reference)
#include <cuda_runtime.h>

// DeChunkLayer: B=4, L=4096, D=1024, fp32 in/out.
// h_t = (1-p_s[t]) h_{t-1} + p_s[t]*hidden[b,t,:]  (t = boundary rank; x from
// UNSORTED hidden at sequential index t — reference quirk, verified R3).
// out rows [pos[t], pos[t+1]) all receive h_t (segment broadcast).
// Single-pass chunked scan with decoupled lookback; no Hs materialization.

#define EPS_F 1e-4f

static constexpr int B = 4;
static constexpr int L = 4096;
static constexpr int D = 1024;
static constexpr int D4 = D / 4;
static constexpr int CT = 32;                 // ranks per chunk
static constexpr int NCH = L / CT;            // 128 chunks (worst case)
static constexpr int S = 2;                   // D slices per chunk
static constexpr int TPB = 128;               // threads per scan block (512 ch)

// Scratch (static device globals)
__device__ float g_ps[B][L];                  // compacted clipped p by rank
__device__ int   g_pos[B][L];                 // token position of rank t
__device__ int   g_Nb[B];                     // boundary count per batch
__device__ float g_aggU[B][S][NCH][TPB * 4];  // chunk aggregate U
__device__ float g_incU[B][S][NCH][TPB * 4];  // inclusive prefix
__device__ float g_aggA[B][S][NCH];           // chunk aggregate A (scalar)
__device__ int   g_flag[B][S][NCH];           // 0=none, 1=agg, 2=inclusive

__device__ __forceinline__ int ld_acquire(const int* p) {
    int v;
    asm volatile("ld.acquire.gpu.b32 %0, [%1];" : "=r"(v) : "l"(p) : "memory");
    return v;
}
__device__ __forceinline__ void st_release(int* p, int v) {
    asm volatile("st.release.gpu.b32 [%0], %1;" :: "l"(p), "r"(v) : "memory");
}

// ---------------------------------------------------------------------------
// K1: zero flags; prefix sum of mask; compact clipped p + positions.
// ---------------------------------------------------------------------------
__global__ __launch_bounds__(1024) void k_setup(const float* __restrict__ bp,
                                                const void* __restrict__ mask) {
    const int b = blockIdx.x;
    const int tid = threadIdx.x;              // 0..1023, 4 tokens each
    const int lane = tid & 31, warp = tid >> 5;

    // reset lookback flags for this batch (S*NCH = 256 ints)
    if (tid < S * NCH) g_flag[b][tid / NCH][tid % NCH] = 0;

    __shared__ int warp_sums[32];

    // ---- mask format detection over first 4096 words (in-bounds all layouts)
    const unsigned int* mw = reinterpret_cast<const unsigned int*>(mask);
    int anyFloat = 0, nonBinary = 0;
    for (int i = tid; i < 4096; i += 1024) {
        unsigned int w = mw[i];
        anyFloat  |= (w == 0x3F800000u);
        nonBinary |= (w > 1u);
    }
    int haveFloat  = __syncthreads_or(anyFloat);
    int haveNonBin = __syncthreads_or(nonBinary);
    const int fmt = haveFloat ? 2 : (haveNonBin ? 0 : 1);  // 2=f32, 1=i32, 0=u8

    int cnt[4];
    if (fmt == 0) {
        uchar4 m4 = reinterpret_cast<const uchar4*>(mask)[b * 1024 + tid];
        cnt[0] = m4.x != 0; cnt[1] = m4.y != 0; cnt[2] = m4.z != 0; cnt[3] = m4.w != 0;
    } else {
        uint4 m4 = reinterpret_cast<const uint4*>(mask)[b * 1024 + tid];
        cnt[0] = m4.x != 0; cnt[1] = m4.y != 0; cnt[2] = m4.z != 0; cnt[3] = m4.w != 0;
    }
    int s = cnt[0] + cnt[1] + cnt[2] + cnt[3];

    int incl = s;
#pragma unroll
    for (int o = 1; o < 32; o <<= 1) {
        int v = __shfl_up_sync(0xffffffffu, incl, o);
        if (lane >= o) incl += v;
    }
    if (lane == 31) warp_sums[warp] = incl;
    __syncthreads();
    if (warp == 0) {
        int ws = warp_sums[lane];
#pragma unroll
        for (int o = 1; o < 32; o <<= 1) {
            int v = __shfl_up_sync(0xffffffffu, ws, o);
            if (lane >= o) ws += v;
        }
        warp_sums[lane] = ws;
    }
    __syncthreads();
    int warp_excl = (warp == 0) ? 0 : warp_sums[warp - 1];
    int run = warp_excl + (incl - s);

    const int base = tid * 4;
#pragma unroll
    for (int k = 0; k < 4; ++k) {
        run += cnt[k];
        int l = base + k;
        if (cnt[k]) {
            float p = bp[(b * L + l) * 2 + 1];
            p = fminf(fmaxf(p, EPS_F), 1.0f - EPS_F);
            int t = run - 1;
            g_ps[b][t]  = p;
            g_pos[b][t] = l;
        }
    }
    if (tid == 1023) g_Nb[b] = run;
}

// ---------------------------------------------------------------------------
// K2: fused scan. Block = (chunk c, batch b, slice z); 128 thr x float4.
// Pass1: chunk aggregate -> publish. Lookback -> carry. Pass2: rescan from
// carry, broadcast h_t to segment rows.
// ---------------------------------------------------------------------------
__global__ __launch_bounds__(TPB) void k_scan(const float* __restrict__ hidden,
                                              float* __restrict__ out) {
    const int c = blockIdx.x, b = blockIdx.y, z = blockIdx.z;
    const int Nb = g_Nb[b];
    const int t0 = c * CT;
    if (t0 >= Nb) return;
    const int tid = threadIdx.x;
    const int nt = min(CT, Nb - t0);

    __shared__ float s_p[CT];
    __shared__ int s_pos[CT + 1];
    __shared__ int s_flag;
    if (tid < nt) {
        s_p[tid]   = g_ps[b][t0 + tid];
        s_pos[tid] = g_pos[b][t0 + tid];
    }
    if (tid == 0) s_pos[nt] = (t0 + nt < Nb) ? g_pos[b][t0 + nt] : L;
    __syncthreads();

    const float4* hid = reinterpret_cast<const float4*>(hidden)
                        + b * L * D4 + z * TPB + tid;

    // ---- pass 1: chunk-local scan (carry-in 0) + aggregate decay product
    float4 h = make_float4(0.f, 0.f, 0.f, 0.f);
    float A = 1.0f;
#pragma unroll 8
    for (int j = 0; j < CT; ++j) {
        if (j >= nt) break;
        float p = s_p[j];
        float dec = 1.0f - p;
        float4 x = hid[(t0 + j) * D4];
        h.x = fmaf(dec, h.x, p * x.x);
        h.y = fmaf(dec, h.y, p * x.y);
        h.z = fmaf(dec, h.z, p * x.z);
        h.w = fmaf(dec, h.w, p * x.w);
        A *= dec;
    }

    float4* aggU = reinterpret_cast<float4*>(&g_aggU[b][z][c][0]);
    float4* incU = reinterpret_cast<float4*>(&g_incU[b][z][c][0]);
    float4 carry = make_float4(0.f, 0.f, 0.f, 0.f);

    if (c > 0) {
        aggU[tid] = h;
        if (tid == 0) g_aggA[b][z][c] = A;
        __threadfence();
        __syncthreads();
        if (tid == 0) st_release(&g_flag[b][z][c], 1);

        // ---- lookback
        float runA = 1.0f;
        int j = c - 1;
        while (true) {
            if (tid == 0) {
                int f;
                do { f = ld_acquire(&g_flag[b][z][j]); } while (f == 0);
                s_flag = f;
            }
            __syncthreads();
            const int f = s_flag;
            __syncthreads();                  // s_flag safe for reuse
            const float4* src = (f == 2)
                ? reinterpret_cast<const float4*>(&g_incU[b][z][j][0])
                : reinterpret_cast<const float4*>(&g_aggU[b][z][j][0]);
            float4 v = src[tid];
            carry.x = fmaf(runA, v.x, carry.x);
            carry.y = fmaf(runA, v.y, carry.y);
            carry.z = fmaf(runA, v.z, carry.z);
            carry.w = fmaf(runA, v.w, carry.w);
            if (f == 2) break;
            runA *= g_aggA[b][z][j];
            if (runA == 0.0f) break;          // exact: residual contribution is 0
            if (--j < 0) break;               // safety (chunk 0 posts flag=2)
        }

        // ---- publish inclusive prefix
        float4 I;
        I.x = fmaf(A, carry.x, h.x);
        I.y = fmaf(A, carry.y, h.y);
        I.z = fmaf(A, carry.z, h.z);
        I.w = fmaf(A, carry.w, h.w);
        incU[tid] = I;
        __threadfence();
        __syncthreads();
        if (tid == 0) st_release(&g_flag[b][z][c], 2);
    } else {
        incU[tid] = h;
        __threadfence();
        __syncthreads();
        if (tid == 0) st_release(&g_flag[b][z][c], 2);
    }

    // ---- pass 2: rescan from carry (x re-reads are L2-hot), broadcast out
    h = carry;
    float4* outp = reinterpret_cast<float4*>(out) + b * L * D4 + z * TPB + tid;
#pragma unroll 4
    for (int j = 0; j < CT; ++j) {
        if (j >= nt) break;
        float p = s_p[j];
        float dec = 1.0f - p;
        float4 x = hid[(t0 + j) * D4];
        h.x = fmaf(dec, h.x, p * x.x);
        h.y = fmaf(dec, h.y, p * x.y);
        h.z = fmaf(dec, h.z, p * x.z);
        h.w = fmaf(dec, h.w, p * x.w);
        const int l0 = s_pos[j];
        const int l1 = s_pos[j + 1];
        float4* dst = outp + l0 * D4;
        for (int l = l0; l < l1; ++l, dst += D4) *dst = h;
    }
}

// ---------------------------------------------------------------------------
extern "C" void kernel_launch(void* const* d_in, const int* in_sizes, int n_in,
                              void* d_out, int out_size) {
    const float* hidden = nullptr;
    const float* bp = nullptr;
    const void* mask = nullptr;
    for (int i = 0; i < n_in; ++i) {
        if (in_sizes[i] == B * L * D)      hidden = (const float*)d_in[i];
        else if (in_sizes[i] == B * L * 2) bp = (const float*)d_in[i];
        else if (in_sizes[i] == B * L)     mask = d_in[i];
    }
    float* out = (float*)d_out;

    k_setup<<<B, 1024>>>(bp, mask);
    k_scan<<<dim3(NCH, B, S), TPB>>>(hidden, out);
}